// round 15
// baseline (speedup 1.0000x reference)
#include <cuda_runtime.h>
#include <cstdint>

// Shapes: depth_map/x_ray [8,1,512,512] fp32 -> out [8,1,128,128,128] fp32
#define NB    8
#define INHW  512
#define RHW   128   // resized H=W
#define ND    128   // depth bins
#define SROWS 134   // histogram rows: depth -3..130 at offset +3
#define WTILE 64    // w columns per block (2 blocks cover w)
#define HSTEP 4     // h rows per block (incremental histogram updates)

// Intermediate buffers (device globals: allocation-free scratch)
__device__ float g_xr[NB * RHW * RHW];
__device__ int   g_dr[NB * RHW * RHW];   // d_idx + 3 (histogram row)

// ---------------------------------------------------------------------------
// packed f32x2 helpers (ptxas will not auto-fuse; PTX only)
// ---------------------------------------------------------------------------
__device__ __forceinline__ unsigned long long pk2(float v) {
    unsigned long long r;
    asm("mov.b64 %0,{%1,%1};" : "=l"(r) : "f"(v));
    return r;
}
__device__ __forceinline__ ulonglong2 addp(ulonglong2 a, ulonglong2 b) {
    ulonglong2 r;
    asm("add.rn.f32x2 %0,%2,%3;\n\t"
        "add.rn.f32x2 %1,%4,%5;"
        : "=l"(r.x), "=l"(r.y)
        : "l"(a.x), "l"(b.x), "l"(a.y), "l"(b.y));
    return r;
}
__device__ __forceinline__ ulonglong2 fmap(ulonglong2 a, unsigned long long w, ulonglong2 c) {
    ulonglong2 r;
    asm("fma.rn.f32x2 %0,%2,%4,%5;\n\t"
        "fma.rn.f32x2 %1,%3,%4,%6;"
        : "=l"(r.x), "=l"(r.y)
        : "l"(a.x), "l"(a.y), "l"(w), "l"(c.x), "l"(c.y));
    return r;
}
__device__ __forceinline__ ulonglong2 mulp(ulonglong2 a, unsigned long long w) {
    ulonglong2 r;
    asm("mul.rn.f32x2 %0,%2,%3;\n\t"
        "mul.rn.f32x2 %1,%4,%3;"
        : "=l"(r.x), "=l"(r.y)
        : "l"(a.x), "l"(w), "l"(a.y));
    return r;
}

// ---------------------------------------------------------------------------
// Kernel 1: jax.image.resize(bilinear, antialias=True) 512->128 both arrays,
// plus depth->index conversion. Block = (h, b), 256 threads:
//   half = tid>>7 owns 4 of the 8 vertical taps; wt = tid&127 = float4 col.
// Horizontal pass: half 0 -> depth index (g_dr = di+3), half 1 -> x_ray.
// Raw triangle weights {1,3,5,7,7,5,3,1}/8, normalized by in-range sum.
// ---------------------------------------------------------------------------
__global__ __launch_bounds__(256) void resize_kernel(const float* __restrict__ depth,
                                                     const float* __restrict__ xray) {
    const int tid  = threadIdx.x;
    const int half = tid >> 7;
    const int wt   = tid & 127;
    const int h    = blockIdx.x;
    const int b    = blockIdx.y;

    __shared__ float tmpd[2][INHW];
    __shared__ float tmpx[2][INHW];

    const float RW[8] = {0.125f, 0.375f, 0.625f, 0.875f,
                         0.875f, 0.625f, 0.375f, 0.125f};

    float4 ad = make_float4(0.f, 0.f, 0.f, 0.f);
    float4 ax = make_float4(0.f, 0.f, 0.f, 0.f);

    #pragma unroll
    for (int tt = 0; tt < 4; ++tt) {
        int t = half * 4 + tt;
        int j = 4 * h - 2 + t;                 // input row (uniform per warp)
        if ((unsigned)j >= (unsigned)INHW) continue;
        float wv = RW[t];
        const float4* drow = (const float4*)(depth + ((size_t)b * INHW + j) * INHW);
        const float4* xrow = (const float4*)(xray  + ((size_t)b * INHW + j) * INHW);
        float4 dv = drow[wt];
        float4 xv = xrow[wt];
        ad.x = fmaf(wv, dv.x, ad.x); ad.y = fmaf(wv, dv.y, ad.y);
        ad.z = fmaf(wv, dv.z, ad.z); ad.w = fmaf(wv, dv.w, ad.w);
        ax.x = fmaf(wv, xv.x, ax.x); ax.y = fmaf(wv, xv.y, ax.y);
        ax.z = fmaf(wv, xv.z, ax.z); ax.w = fmaf(wv, xv.w, ax.w);
    }
    ((float4*)tmpd[half])[wt] = ad;
    ((float4*)tmpx[half])[wt] = ax;

    float wsv = 0.f;
    #pragma unroll
    for (int t = 0; t < 8; ++t) {
        int j = 4 * h - 2 + t;
        if ((unsigned)j < (unsigned)INHW) wsv += RW[t];
    }
    __syncthreads();

    const float* buf0 = half ? tmpx[0] : tmpd[0];
    const float* buf1 = half ? tmpx[1] : tmpd[1];

    float acc = 0.f, wsh = 0.f;
    #pragma unroll
    for (int t = 0; t < 8; ++t) {
        int c = 4 * wt - 2 + t;                // input col
        if ((unsigned)c < (unsigned)INHW) {
            float wv = RW[t];
            wsh += wv;
            acc = fmaf(wv, buf0[c] + buf1[c], acc);
        }
    }
    float val = acc / (wsv * wsh);

    int idx = (b * RHW + h) * RHW + wt;
    if (half == 0) {
        // d_idx = clip(int((depth/100)*127), 0, 127), stored as di+3
        int di = (int)((val / 100.f) * 127.f);
        di = di < 0 ? 0 : (di > ND - 1 ? ND - 1 : di);
        g_dr[idx] = di + 3;
    } else {
        g_xr[idx] = val;
    }
}

// ---------------------------------------------------------------------------
// Kernel 2: fused gaussian depth splat + 3x3x3 avg pool (/27, include_pad).
//   s[d][w] = 9-neighbor weighted histogram (3x3 spatial pool folded in)
//   out[d]  = (W7 (*) s)[d],  W7 = box3 (*) gauss5, /27 folded in, with exact
//   corrections at d=0 / d=127 for the excluded pool taps p[-1]/p[128].
// Block = (hb, wb, b): 4 consecutive h rows x 64-wide w half. Tile s is
// [134][64] (34KB): zeroed + built ONCE, then updated incrementally per h:
//   s_{h+1} = s_h - rowhist(h-1) + rowhist(h+2)   (6 RMWs/column vs 9).
// 256 threads; gather thread = (wq = tid&15 -> 4 w's, dq = tid>>4 -> 8 d's):
// 7-row float4 sliding window, packed f32x2 math, LDS.128 in, STG.128 out.
// Row stride 64 floats => bank = w%32: conflict-free scatter & updates.
// Row preloads for the next update overlap the gather phase (2 syncs per h).
// ---------------------------------------------------------------------------
__global__ __launch_bounds__(256) void splat_pool_kernel(float* __restrict__ out) {
    extern __shared__ float s[];               // [SROWS][WTILE], 34304 B
    __shared__ float bx[3][WTILE + 2];
    __shared__ int   bd[3][WTILE + 2];
    __shared__ float rx[2][WTILE + 2];
    __shared__ int   rd[2][WTILE + 2];

    const int hb  = blockIdx.x;                // 0..31
    const int wb  = blockIdx.y;                // 0..1
    const int b   = blockIdx.z;                // 0..7
    const int tid = threadIdx.x;
    const int h0  = hb * HSTEP;
    const int w0  = wb * WTILE;

    // Zero the tile (float4)
    float4* s4 = (float4*)s;
    for (int i = tid; i < SROWS * WTILE / 4; i += 256)
        s4[i] = make_float4(0.f, 0.f, 0.f, 0.f);

    // Load build rows h0-1, h0, h0+1 (halo cols w0-1 .. w0+64)
    if (tid < 3 * (WTILE + 2)) {
        int r = tid / (WTILE + 2), c = tid - r * (WTILE + 2);
        int hh = h0 + r - 1, ww = w0 + c - 1;
        bool v = ((unsigned)hh < (unsigned)RHW) && ((unsigned)ww < (unsigned)RHW);
        int idx = (b * RHW + (v ? hh : 0)) * RHW + (v ? ww : 0);
        bx[r][c] = v ? g_xr[idx] : 0.f;
        bd[r][c] = v ? g_dr[idx] : 3;
    }
    __syncthreads();

    // Build: 9 RMWs per owned column (unique owner -> no atomics)
    if (tid < WTILE) {
        const int w = tid;
        #pragma unroll
        for (int r = 0; r < 3; ++r)
            #pragma unroll
            for (int dw = 0; dw < 3; ++dw)
                s[(bd[r][w + dw] << 6) + w] += bx[r][w + dw];
    }
    __syncthreads();

    // 7-tap combined weights (symmetric), 1/27 folded in
    const float e1 = 0.60653065971263342f;     // exp(-0.5)
    const float e2 = 0.13533528323661270f;     // exp(-2)
    const float G0 = 1.f / 27.f, G1 = e1 / 27.f, G2 = e2 / 27.f;
    const unsigned long long W0  = pk2(G0 + 2.f * G1);
    const unsigned long long W1  = pk2(G0 + G1 + G2);
    const unsigned long long W2  = pk2(G1 + G2);
    const unsigned long long W3  = pk2(G2);
    const unsigned long long nG1 = pk2(-G1);
    const unsigned long long nG2 = pk2(-G2);

    const int wq = tid & 15;                   // float4 w-group within tile
    const int dq = tid >> 4;                   // 16 depth groups x 8 depths
    const int d0 = dq << 3;
    const ulonglong2* srow = (const ulonglong2*)s;   // row = 16 ulonglong2

    #pragma unroll
    for (int hi = 0; hi < HSTEP; ++hi) {
        const int h = h0 + hi;

        // ---- gather: 8 outputs per thread via sliding 7-row window ----
        ulonglong2 v[7];
        #pragma unroll
        for (int k = 0; k < 7; ++k) v[k] = srow[(d0 + k) * 16 + wq];

        float* op = out + ((size_t)b * ND + d0) * (RHW * RHW)
                        + (size_t)h * RHW + w0 + (wq << 2);
        #pragma unroll
        for (int i = 0; i < 8; ++i) {
            ulonglong2 c = mulp(v[3], W0);
            c = fmap(addp(v[2], v[4]), W1, c);
            c = fmap(addp(v[1], v[5]), W2, c);
            c = fmap(addp(v[0], v[6]), W3, c);
            if (dq == 0 && i == 0) {           // d==0: remove p[-1]
                c = fmap(v[3], nG1, c);
                c = fmap(v[4], nG2, c);
            }
            if (dq == 15 && i == 7) {          // d==127: remove p[128]
                c = fmap(v[3], nG1, c);
                c = fmap(v[2], nG2, c);
            }
            *(ulonglong2*)op = c;              // STG.128, coalesced
            op += RHW * RHW;
            if (i < 7) {
                #pragma unroll
                for (int k = 0; k < 6; ++k) v[k] = v[k + 1];
                v[6] = srow[(d0 + i + 7) * 16 + wq];   // max row 133
            }
        }

        if (hi < HSTEP - 1) {
            // ---- preload update rows (overlaps gather; disjoint smem) ----
            if (tid < 2 * (WTILE + 2)) {
                int which = tid >= (WTILE + 2);        // 0: subtract h-1, 1: add h+2
                int c  = which ? tid - (WTILE + 2) : tid;
                int hh = which ? h + 2 : h - 1;
                int ww = w0 + c - 1;
                bool vv = ((unsigned)hh < (unsigned)RHW) && ((unsigned)ww < (unsigned)RHW);
                int idx = (b * RHW + (vv ? hh : 0)) * RHW + (vv ? ww : 0);
                rx[which][c] = vv ? g_xr[idx] : 0.f;
                rd[which][c] = vv ? g_dr[idx] : 3;
            }
            __syncthreads();                   // gathers done + preload done
            if (tid < WTILE) {
                const int w = tid;
                #pragma unroll
                for (int dw = 0; dw < 3; ++dw) {
                    s[(rd[0][w + dw] << 6) + w] -= rx[0][w + dw];
                    s[(rd[1][w + dw] << 6) + w] += rx[1][w + dw];
                }
            }
            __syncthreads();                   // s updated for h+1
        }
    }
}

// ---------------------------------------------------------------------------
extern "C" void kernel_launch(void* const* d_in, const int* in_sizes, int n_in,
                              void* d_out, int out_size) {
    const float* depth = (const float*)d_in[0];   // [8,1,512,512] fp32
    const float* xray  = (const float*)d_in[1];   // [8,1,512,512] fp32
    float* out = (float*)d_out;                   // [8,1,128,128,128] fp32

    (void)in_sizes; (void)n_in; (void)out_size;

    cudaFuncSetAttribute(splat_pool_kernel,
                         cudaFuncAttributeMaxDynamicSharedMemorySize,
                         SROWS * WTILE * (int)sizeof(float));

    dim3 rgrid(RHW, NB);
    resize_kernel<<<rgrid, 256>>>(depth, xray);

    dim3 sgrid(RHW / HSTEP, RHW / WTILE, NB);
    splat_pool_kernel<<<sgrid, 256, SROWS * WTILE * sizeof(float)>>>(out);
}